// round 13
// baseline (speedup 1.0000x reference)
#include <cuda_runtime.h>
#include <cuda_bf16.h>
#include <cstdint>

// Inputs (metadata order):
//   0: x          float32 [200000]
//   1: Param_W    float32 [1000000]
//   2: Param_b    float32 [500]
//   3: src        int32   [12800000]
//   4: dst        int32   [12800000]
//   5: weight_idx int32   [12800000]
//   6: node_label int32   [200000]
// Output: y float32 [200000]

// Vectorized bias init: 4 nodes per thread (int4 label load, float4 y store).
// Implicit PDL trigger at kernel completion only (explicit early trigger
// correlated with a 1.5x slower machine state in R10; do not reintroduce).
__global__ void init_bias_vec4_kernel(const float* __restrict__ Param_b,
                                      const int4* __restrict__ node_label4,
                                      float4* __restrict__ y4,
                                      int n_vec) {
    int i = blockIdx.x * blockDim.x + threadIdx.x;
    if (i < n_vec) {
        int4 l = node_label4[i];
        float4 v;
        v.x = __ldg(&Param_b[l.x]);
        v.y = __ldg(&Param_b[l.y]);
        v.z = __ldg(&Param_b[l.z]);
        v.w = __ldg(&Param_b[l.w]);
        y4[i] = v;
    }
}

__global__ void init_bias_tail_kernel(const float* __restrict__ Param_b,
                                      const int* __restrict__ node_label,
                                      float* __restrict__ y,
                                      int start, int n_nodes) {
    int i = start + blockIdx.x * blockDim.x + threadIdx.x;
    if (i < n_nodes) {
        y[i] = __ldg(&Param_b[node_label[i]]);
    }
}

// Edge kernel (converged floor shape): 256-thread CTAs, 8/SM, straight-line
// body, 4 edges/thread, exact-cover grid. All loads issued up front
// (3 streaming LDG.128 + 8 random 32-bit gathers), one unconditional PDL
// sync, then 4 predicated RED.E.ADD scatters. PDL launch overlaps the load
// phase with the init kernel's execution.
__global__ void __launch_bounds__(256, 8)
edge_scatter_vec4_pdl_kernel(const float* __restrict__ x,
                             const float* __restrict__ Param_W,
                             const int4* __restrict__ src4,
                             const int4* __restrict__ dst4,
                             const int4* __restrict__ wi4,
                             float* __restrict__ y,
                             int n_vec) {
    int i = blockIdx.x * blockDim.x + threadIdx.x;
    bool active = i < n_vec;

    float m0 = 0.f, m1 = 0.f, m2 = 0.f, m3 = 0.f;
    int4 d = make_int4(0, 0, 0, 0);
    if (active) {
        int4 s = src4[i];
        int4 w = wi4[i];
        d = dst4[i];

        m0 = __ldg(&Param_W[w.x]) * __ldg(&x[s.x]);
        m1 = __ldg(&Param_W[w.y]) * __ldg(&x[s.y]);
        m2 = __ldg(&Param_W[w.z]) * __ldg(&x[s.z]);
        m3 = __ldg(&Param_W[w.w]) * __ldg(&x[s.w]);
    }

#if __CUDA_ARCH__ >= 900
    cudaGridDependencySynchronize();
#endif

    if (active) {
        atomicAdd(&y[d.x], m0);
        atomicAdd(&y[d.y], m1);
        atomicAdd(&y[d.z], m2);
        atomicAdd(&y[d.w], m3);
    }
}

// Scalar tail for edge counts not divisible by 4 (not hit for 12.8M).
__global__ void edge_scatter_tail_kernel(const float* __restrict__ x,
                                         const float* __restrict__ Param_W,
                                         const int* __restrict__ src,
                                         const int* __restrict__ dst,
                                         const int* __restrict__ wi,
                                         float* __restrict__ y,
                                         int start, int n_edges) {
    int i = start + blockIdx.x * blockDim.x + threadIdx.x;
    if (i < n_edges) {
        float m = __ldg(&Param_W[wi[i]]) * __ldg(&x[src[i]]);
        atomicAdd(&y[dst[i]], m);
    }
}

extern "C" void kernel_launch(void* const* d_in, const int* in_sizes, int n_in,
                              void* d_out, int out_size) {
    const float* x          = (const float*)d_in[0];
    const float* Param_W    = (const float*)d_in[1];
    const float* Param_b    = (const float*)d_in[2];
    const int*   src        = (const int*)d_in[3];
    const int*   dst        = (const int*)d_in[4];
    const int*   weight_idx = (const int*)d_in[5];
    const int*   node_label = (const int*)d_in[6];
    float* y = (float*)d_out;

    int n_nodes = in_sizes[0];
    int n_edges = in_sizes[3];

    // 1) y = Param_b[node_label]  (vectorized 4 nodes/thread)
    {
        int n_nvec = n_nodes / 4;
        if (n_nvec > 0) {
            int threads = 256;
            int blocks = (n_nvec + threads - 1) / threads;
            init_bias_vec4_kernel<<<blocks, threads>>>(
                Param_b, (const int4*)node_label, (float4*)y, n_nvec);
        }
        int tstart = n_nvec * 4;
        int trem = n_nodes - tstart;
        if (trem > 0) {
            int threads = 256;
            int blocks = (trem + threads - 1) / threads;
            init_bias_tail_kernel<<<blocks, threads>>>(
                Param_b, node_label, y, tstart, n_nodes);
        }
    }

    // 2) scatter-add messages: one-shot exact-cover grid, 4 edges/thread,
    //    PDL launch so the load phase overlaps init.
    int n_vec = n_edges / 4;
    if (n_vec > 0) {
        const int threads = 256;
        long long want = ((long long)n_vec + threads - 1) / threads;
        long long cap = 65535LL * 1024LL;
        int blocks = (int)(want > cap ? cap : want);

        cudaLaunchConfig_t cfg = {};
        cfg.gridDim = dim3((unsigned)blocks, 1, 1);
        cfg.blockDim = dim3(threads, 1, 1);
        cfg.dynamicSmemBytes = 0;
        cfg.stream = 0;

        cudaLaunchAttribute attrs[1];
        attrs[0].id = cudaLaunchAttributeProgrammaticStreamSerialization;
        attrs[0].val.programmaticStreamSerializationAllowed = 1;
        cfg.attrs = attrs;
        cfg.numAttrs = 1;

        cudaError_t e = cudaLaunchKernelEx(&cfg, edge_scatter_vec4_pdl_kernel,
                                           x, Param_W,
                                           (const int4*)src, (const int4*)dst,
                                           (const int4*)weight_idx,
                                           y, n_vec);
        if (e != cudaSuccess) {
            // Fallback: plain launch (gridDepSync is a no-op after full
            // serialization).
            edge_scatter_vec4_pdl_kernel<<<blocks, threads>>>(
                x, Param_W,
                (const int4*)src, (const int4*)dst, (const int4*)weight_idx,
                y, n_vec);
        }
    }
    int tail_start = n_vec * 4;
    int tail = n_edges - tail_start;
    if (tail > 0) {
        int threads = 256;
        int blocks = (tail + threads - 1) / threads;
        edge_scatter_tail_kernel<<<blocks, threads>>>(
            x, Param_W, src, dst, weight_idx, y, tail_start, n_edges);
    }
}

// round 14
// speedup vs baseline: 1.0752x; 1.0752x over previous
#include <cuda_runtime.h>
#include <cuda_bf16.h>
#include <cstdint>

// Inputs (metadata order):
//   0: x          float32 [200000]
//   1: Param_W    float32 [1000000]
//   2: Param_b    float32 [500]
//   3: src        int32   [12800000]
//   4: dst        int32   [12800000]
//   5: weight_idx int32   [12800000]
//   6: node_label int32   [200000]
// Output: y float32 [200000]
//
// Structure: y is memset to 0, then ONE fused kernel does both the edge
// scatter (RED.E.ADD) and the per-node bias add (also RED.E.ADD). Since all
// contributions are atomic adds into a zeroed buffer, no intra-kernel
// ordering is needed and the init-gather kernel + PDL dependency disappear
// from the critical path.

// Fused kernel (proven floor shape for the edge part): 256-thread CTAs,
// 8/SM, straight-line body, 4 edges/thread, exact-cover grid.
// Threads with i < n_node_vec additionally add the bias for 4 nodes.
__global__ void __launch_bounds__(256, 8)
edge_scatter_fused_kernel(const float* __restrict__ x,
                          const float* __restrict__ Param_W,
                          const float* __restrict__ Param_b,
                          const int4* __restrict__ src4,
                          const int4* __restrict__ dst4,
                          const int4* __restrict__ wi4,
                          const int4* __restrict__ node_label4,
                          float* __restrict__ y,
                          int n_vec,
                          int n_node_vec) {
    int i = blockIdx.x * blockDim.x + threadIdx.x;

    if (i < n_vec) {
        int4 s = src4[i];
        int4 w = wi4[i];
        int4 d = dst4[i];

        float m0 = __ldg(&Param_W[w.x]) * __ldg(&x[s.x]);
        float m1 = __ldg(&Param_W[w.y]) * __ldg(&x[s.y]);
        float m2 = __ldg(&Param_W[w.z]) * __ldg(&x[s.z]);
        float m3 = __ldg(&Param_W[w.w]) * __ldg(&x[s.w]);

        atomicAdd(&y[d.x], m0);
        atomicAdd(&y[d.y], m1);
        atomicAdd(&y[d.z], m2);
        atomicAdd(&y[d.w], m3);
    }

    // Bias add for 4 consecutive nodes (only first n_node_vec threads;
    // 50K of 3.2M threads -> negligible extra per-thread work).
    if (i < n_node_vec) {
        int4 l = node_label4[i];
        int base = i * 4;
        atomicAdd(&y[base + 0], __ldg(&Param_b[l.x]));
        atomicAdd(&y[base + 1], __ldg(&Param_b[l.y]));
        atomicAdd(&y[base + 2], __ldg(&Param_b[l.z]));
        atomicAdd(&y[base + 3], __ldg(&Param_b[l.w]));
    }
}

// Scalar tails (not hit for these sizes: 12.8M % 4 == 0, 200K % 4 == 0).
__global__ void edge_scatter_tail_kernel(const float* __restrict__ x,
                                         const float* __restrict__ Param_W,
                                         const int* __restrict__ src,
                                         const int* __restrict__ dst,
                                         const int* __restrict__ wi,
                                         float* __restrict__ y,
                                         int start, int n_edges) {
    int i = start + blockIdx.x * blockDim.x + threadIdx.x;
    if (i < n_edges) {
        float m = __ldg(&Param_W[wi[i]]) * __ldg(&x[src[i]]);
        atomicAdd(&y[dst[i]], m);
    }
}

__global__ void bias_tail_kernel(const float* __restrict__ Param_b,
                                 const int* __restrict__ node_label,
                                 float* __restrict__ y,
                                 int start, int n_nodes) {
    int i = start + blockIdx.x * blockDim.x + threadIdx.x;
    if (i < n_nodes) {
        atomicAdd(&y[i], __ldg(&Param_b[node_label[i]]));
    }
}

extern "C" void kernel_launch(void* const* d_in, const int* in_sizes, int n_in,
                              void* d_out, int out_size) {
    const float* x          = (const float*)d_in[0];
    const float* Param_W    = (const float*)d_in[1];
    const float* Param_b    = (const float*)d_in[2];
    const int*   src        = (const int*)d_in[3];
    const int*   dst        = (const int*)d_in[4];
    const int*   weight_idx = (const int*)d_in[5];
    const int*   node_label = (const int*)d_in[6];
    float* y = (float*)d_out;

    int n_nodes = in_sizes[0];
    int n_edges = in_sizes[3];

    // 1) y = 0 (fast memset node; the fused kernel's only dependency)
    cudaMemsetAsync(y, 0, (size_t)out_size * sizeof(float));

    // 2) fused scatter-add (edges) + bias add (nodes), one kernel.
    int n_vec = n_edges / 4;
    int n_node_vec = n_nodes / 4;
    {
        const int threads = 256;
        int work = n_vec > n_node_vec ? n_vec : n_node_vec;
        long long want = ((long long)work + threads - 1) / threads;
        long long cap = 2147483647LL;
        int blocks = (int)(want > cap ? cap : want);
        if (blocks < 1) blocks = 1;
        edge_scatter_fused_kernel<<<blocks, threads>>>(
            x, Param_W, Param_b,
            (const int4*)src, (const int4*)dst, (const int4*)weight_idx,
            (const int4*)node_label,
            y, n_vec, n_node_vec);
    }

    // 3) tails (no-ops for these sizes)
    int e_start = n_vec * 4;
    int e_rem = n_edges - e_start;
    if (e_rem > 0) {
        int threads = 256;
        int blocks = (e_rem + threads - 1) / threads;
        edge_scatter_tail_kernel<<<blocks, threads>>>(
            x, Param_W, src, dst, weight_idx, y, e_start, n_edges);
    }
    int b_start = n_node_vec * 4;
    int b_rem = n_nodes - b_start;
    if (b_rem > 0) {
        int threads = 256;
        int blocks = (b_rem + threads - 1) / threads;
        bias_tail_kernel<<<blocks, threads>>>(
            Param_b, node_label, y, b_start, n_nodes);
    }
}

// round 15
// speedup vs baseline: 1.0907x; 1.0144x over previous
#include <cuda_runtime.h>
#include <cuda_bf16.h>
#include <cstdint>

// Inputs (metadata order):
//   0: x          float32 [200000]
//   1: Param_W    float32 [1000000]
//   2: Param_b    float32 [500]
//   3: src        int32   [12800000]
//   4: dst        int32   [12800000]
//   5: weight_idx int32   [12800000]
//   6: node_label int32   [200000]
// Output: y float32 [200000]
//
// Structure: y memset to 0, then ONE fused kernel does both the edge scatter
// and the per-node bias add, all via RED.E.ADD into the zeroed buffer (order
// free). The bias work rides on the LAST 50K threads (last ~196 CTAs), which
// execute in the final partial wave (~660/1184 slots used) — i.e. on
// otherwise-idle machine resources — instead of stretching wave 1.

__global__ void __launch_bounds__(256, 8)
edge_scatter_fused_kernel(const float* __restrict__ x,
                          const float* __restrict__ Param_W,
                          const float* __restrict__ Param_b,
                          const int4* __restrict__ src4,
                          const int4* __restrict__ dst4,
                          const int4* __restrict__ wi4,
                          const int4* __restrict__ node_label4,
                          float* __restrict__ y,
                          int n_vec,
                          int bias_offset,   // = n_vec - n_node_vec (>=0)
                          int n_node_vec) {
    int i = blockIdx.x * blockDim.x + threadIdx.x;

    if (i < n_vec) {
        int4 s = src4[i];
        int4 w = wi4[i];
        int4 d = dst4[i];

        float m0 = __ldg(&Param_W[w.x]) * __ldg(&x[s.x]);
        float m1 = __ldg(&Param_W[w.y]) * __ldg(&x[s.y]);
        float m2 = __ldg(&Param_W[w.z]) * __ldg(&x[s.z]);
        float m3 = __ldg(&Param_W[w.w]) * __ldg(&x[s.w]);

        atomicAdd(&y[d.x], m0);
        atomicAdd(&y[d.y], m1);
        atomicAdd(&y[d.z], m2);
        atomicAdd(&y[d.w], m3);
    }

    // Bias add for 4 consecutive nodes, carried by the tail threads
    // (j in [0, n_node_vec) for i in [bias_offset, bias_offset + n_node_vec)).
    int j = i - bias_offset;
    if (j >= 0 && j < n_node_vec) {
        int4 l = node_label4[j];
        int base = j * 4;
        atomicAdd(&y[base + 0], __ldg(&Param_b[l.x]));
        atomicAdd(&y[base + 1], __ldg(&Param_b[l.y]));
        atomicAdd(&y[base + 2], __ldg(&Param_b[l.z]));
        atomicAdd(&y[base + 3], __ldg(&Param_b[l.w]));
    }
}

// Scalar tails (not hit for these sizes: 12.8M % 4 == 0, 200K % 4 == 0).
__global__ void edge_scatter_tail_kernel(const float* __restrict__ x,
                                         const float* __restrict__ Param_W,
                                         const int* __restrict__ src,
                                         const int* __restrict__ dst,
                                         const int* __restrict__ wi,
                                         float* __restrict__ y,
                                         int start, int n_edges) {
    int i = start + blockIdx.x * blockDim.x + threadIdx.x;
    if (i < n_edges) {
        float m = __ldg(&Param_W[wi[i]]) * __ldg(&x[src[i]]);
        atomicAdd(&y[dst[i]], m);
    }
}

__global__ void bias_tail_kernel(const float* __restrict__ Param_b,
                                 const int* __restrict__ node_label,
                                 float* __restrict__ y,
                                 int start, int n_nodes) {
    int i = start + blockIdx.x * blockDim.x + threadIdx.x;
    if (i < n_nodes) {
        atomicAdd(&y[i], __ldg(&Param_b[node_label[i]]));
    }
}

extern "C" void kernel_launch(void* const* d_in, const int* in_sizes, int n_in,
                              void* d_out, int out_size) {
    const float* x          = (const float*)d_in[0];
    const float* Param_W    = (const float*)d_in[1];
    const float* Param_b    = (const float*)d_in[2];
    const int*   src        = (const int*)d_in[3];
    const int*   dst        = (const int*)d_in[4];
    const int*   weight_idx = (const int*)d_in[5];
    const int*   node_label = (const int*)d_in[6];
    float* y = (float*)d_out;

    int n_nodes = in_sizes[0];
    int n_edges = in_sizes[3];

    // 1) y = 0 (memset node; the fused kernel's only dependency)
    cudaMemsetAsync(y, 0, (size_t)out_size * sizeof(float));

    // 2) fused scatter-add (edges) + tail-wave bias add (nodes), one kernel.
    int n_vec = n_edges / 4;
    int n_node_vec = n_nodes / 4;
    int bias_offset = n_vec - n_node_vec;
    if (bias_offset < 0) bias_offset = 0;  // degenerate: fewer edge-threads than node groups
    {
        const int threads = 256;
        long long total_work = (long long)bias_offset + n_node_vec;
        if (total_work < n_vec) total_work = n_vec;
        long long want = (total_work + threads - 1) / threads;
        long long cap = 2147483647LL;
        int blocks = (int)(want > cap ? cap : want);
        if (blocks < 1) blocks = 1;
        edge_scatter_fused_kernel<<<blocks, threads>>>(
            x, Param_W, Param_b,
            (const int4*)src, (const int4*)dst, (const int4*)weight_idx,
            (const int4*)node_label,
            y, n_vec, bias_offset, n_node_vec);
    }

    // 3) tails (no-ops for these sizes)
    int e_start = n_vec * 4;
    int e_rem = n_edges - e_start;
    if (e_rem > 0) {
        int threads = 256;
        int blocks = (e_rem + threads - 1) / threads;
        edge_scatter_tail_kernel<<<blocks, threads>>>(
            x, Param_W, src, dst, weight_idx, y, e_start, n_edges);
    }
    int b_start = n_node_vec * 4;
    int b_rem = n_nodes - b_start;
    if (b_rem > 0) {
        int threads = 256;
        int blocks = (b_rem + threads - 1) / threads;
        bias_tail_kernel<<<blocks, threads>>>(
            Param_b, node_label, y, b_start, n_nodes);
    }
}